// round 15
// baseline (speedup 1.0000x reference)
#include <cuda_runtime.h>
#include <cuda_fp16.h>

// ---- static problem shape -------------------------------------------------
#define BATCH   8
#define HH      32
#define WWID    32
#define CDIM    768
#define NHEADS  12
#define HD      64
#define SEQ     1024
#define BHEADS  96
#define N_QKV   2304

// ---- scratch (device globals; allocation is forbidden) ---------------------
__device__ __align__(256) __half g_Q  [(size_t)BHEADS * SEQ * HD];   // pre-scaled 1/8
__device__ __align__(256) __half g_K  [(size_t)BHEADS * SEQ * HD];
__device__ __align__(256) __half g_Vt [(size_t)BHEADS * HD * SEQ];   // [bh][d][s]
__device__ __align__(256) float  g_RH [(size_t)BHEADS * SEQ * HH];
__device__ __align__(256) float  g_RW [(size_t)BHEADS * SEQ * WWID];
__device__ __align__(256) __half g_ATT[(size_t)BATCH * SEQ * CDIM];
__device__ __align__(256) __half g_X  [(size_t)BATCH * SEQ * CDIM];
__device__ __align__(256) __half g_W1t[(size_t)N_QKV * CDIM];        // [n][k]
__device__ __align__(256) __half g_W2t[(size_t)CDIM * CDIM];         // [n][k]

// ---- helpers ---------------------------------------------------------------
__device__ __forceinline__ unsigned pack_half2(float lo, float hi) {
    unsigned r;
    asm("cvt.rn.f16x2.f32 %0, %1, %2;" : "=r"(r) : "f"(hi), "f"(lo));
    return r;
}
__device__ __forceinline__ void mma_f16(float c[4], const unsigned a[4],
                                        const unsigned b0, const unsigned b1) {
    asm volatile(
        "mma.sync.aligned.m16n8k16.row.col.f32.f16.f16.f32 "
        "{%0,%1,%2,%3},{%4,%5,%6,%7},{%8,%9},{%0,%1,%2,%3};"
        : "+f"(c[0]), "+f"(c[1]), "+f"(c[2]), "+f"(c[3])
        : "r"(a[0]), "r"(a[1]), "r"(a[2]), "r"(a[3]), "r"(b0), "r"(b1));
}

// ===========================================================================
// Pre-pass 1: fp32 -> fp16 elementwise (hidden).
// ===========================================================================
__global__ void __launch_bounds__(256) cvt_kernel(
    const float4* __restrict__ src, uint2* __restrict__ dst, int n4)
{
    const int i = blockIdx.x * 256 + threadIdx.x;
    if (i < n4) {
        float4 v = src[i];
        dst[i] = make_uint2(pack_half2(v.x, v.y), pack_half2(v.z, v.w));
    }
}

// ===========================================================================
// Pre-pass 2: transpose + convert weights.  Wt[n][k] = fp16(W[k][n]).
// ===========================================================================
__global__ void __launch_bounds__(256) transpose_cvt_kernel(
    const float* __restrict__ W, __half* __restrict__ Wt, int K, int N)
{
    __shared__ float tile[32][33];
    const int n0 = blockIdx.x * 32, k0 = blockIdx.y * 32;
    const int tx = threadIdx.x & 31, ty = threadIdx.x >> 5;
#pragma unroll
    for (int r = 0; r < 32; r += 8)
        tile[ty + r][tx] = W[(size_t)(k0 + ty + r) * N + n0 + tx];
    __syncthreads();
#pragma unroll
    for (int r = 0; r < 32; r += 8)
        Wt[(size_t)(n0 + ty + r) * K + k0 + tx] = __float2half(tile[tx][ty + r]);
}

// ===========================================================================
// fp16 GEMM:  out = X @ W + bias, computed transposed (D = W^T @ X^T).
// Block 128N x 128M, 4 warps, warp tile 64N x 64M (B-frag reused x4).
// k-step 64; LDGs issued before the barrier (overlap prev tile's compute).
// ===========================================================================
template<bool QKV_SCATTER>
__global__ void __launch_bounds__(128, 2) gemm_f16_kernel(
    const __half* __restrict__ X, const __half* __restrict__ Wt,
    const float* __restrict__ bias, float* __restrict__ out)
{
    __shared__ unsigned Wsm[128 * 36];
    __shared__ unsigned Xsm[128 * 36];

    const int t = threadIdx.x;
    const int w = t >> 5, lane = t & 31, g = lane >> 2, t4 = lane & 3;
    const int warpN = (w & 1) * 64, warpM = (w >> 1) * 64;
    const int bn = blockIdx.x * 128, bm = blockIdx.y * 128;

    float acc[4][8][4] = {};

    for (int i = 0; i < 12; i++) {
        uint4 wreg[8], xreg[8];
#pragma unroll
        for (int j = 0; j < 8; j++) {
            const int idx = t + 128 * j;
            const int row = idx >> 3, u4 = idx & 7;
            wreg[j] = *(const uint4*)(Wt + (size_t)(bn + row) * CDIM
                                      + i * 64 + u4 * 8);
            xreg[j] = *(const uint4*)(X + (size_t)(bm + row) * CDIM
                                      + i * 64 + u4 * 8);
        }
        __syncthreads();
#pragma unroll
        for (int j = 0; j < 8; j++) {
            const int idx = t + 128 * j;
            const int row = idx >> 3, u4 = idx & 7;
            *(uint4*)&Wsm[row * 36 + u4 * 4] = wreg[j];
            *(uint4*)&Xsm[row * 36 + u4 * 4] = xreg[j];
        }
        __syncthreads();

#pragma unroll
        for (int ks = 0; ks < 4; ks++) {
            const int kw = ks * 8;
            unsigned a[4][4];
#pragma unroll
            for (int mt = 0; mt < 4; mt++) {
                const int nr = warpN + mt * 16 + g;
                a[mt][0] = Wsm[nr * 36 + kw + t4];
                a[mt][1] = Wsm[(nr + 8) * 36 + kw + t4];
                a[mt][2] = Wsm[nr * 36 + kw + t4 + 4];
                a[mt][3] = Wsm[(nr + 8) * 36 + kw + t4 + 4];
            }
#pragma unroll
            for (int nt = 0; nt < 8; nt++) {
                const int mr = (warpM + nt * 8 + g) * 36 + kw;
                const unsigned b0 = Xsm[mr + t4];
                const unsigned b1 = Xsm[mr + t4 + 4];
#pragma unroll
                for (int mt = 0; mt < 4; mt++)
                    mma_f16(acc[mt][nt], a[mt], b0, b1);
            }
        }
    }

#pragma unroll
    for (int mt = 0; mt < 4; mt++) {
#pragma unroll
        for (int nt = 0; nt < 8; nt++) {
            const int ncol0 = bn + warpN + mt * 16 + g;
            const int mrow  = bm + warpM + nt * 8 + 2 * t4;
#pragma unroll
            for (int h8 = 0; h8 < 2; h8++) {
                const int ncol = ncol0 + h8 * 8;
                const float bs = __ldg(bias + ncol);
                const float v0 = acc[mt][nt][h8 * 2 + 0] + bs;
                const float v1 = acc[mt][nt][h8 * 2 + 1] + bs;
                if (QKV_SCATTER) {
                    const int which = ncol / CDIM;
                    const int rem   = ncol - which * CDIM;
                    const int h = rem >> 6, d = rem & 63;
                    const int b_ = mrow >> 10, s_ = mrow & 1023;
                    const int bh = b_ * NHEADS + h;
                    if (which == 2) {
                        __half* vp = g_Vt + ((size_t)bh * HD + d) * SEQ + s_;
                        vp[0] = __float2half(v0);
                        vp[1] = __float2half(v1);
                    } else {
                        __half* dst = (which == 0) ? g_Q : g_K;
                        const float sc = (which == 0) ? 0.125f : 1.0f;
                        const size_t base =
                            ((size_t)bh * SEQ + s_) * HD + d;
                        dst[base]      = __float2half(v0 * sc);
                        dst[base + HD] = __float2half(v1 * sc);
                    }
                } else {
                    out[(size_t)mrow * CDIM + ncol]       = v0;
                    out[(size_t)(mrow + 1) * CDIM + ncol] = v1;
                }
            }
        }
    }
}

// ===========================================================================
// relative-position bias (Q fp16, pre-scaled 1/8 -> output x8).
// ===========================================================================
__global__ void __launch_bounds__(256) rel_kernel(
    const float* __restrict__ rph, const float* __restrict__ rpw)
{
    __shared__ float Qs[32 * 65];
    __shared__ float Hs[32 * 65];
    __shared__ float Wt[63 * 65];

    const int bh = blockIdx.y;
    const int qh = blockIdx.x;
    const int t  = threadIdx.x;

    const __half* Qg = g_Q + ((size_t)bh * SEQ + qh * 32) * HD;
#pragma unroll
    for (int i = t; i < 2048; i += 256) {
        const int r = i >> 6, d = i & 63;
        Qs[r * 65 + d] = __half2float(Qg[i]);
        Hs[r * 65 + d] = __ldg(rph + (qh + r) * 64 + d);
    }
    for (int i = t; i < 4032; i += 256) {
        const int r = i >> 6, d = i & 63;
        Wt[r * 65 + d] = __ldg(rpw + i);
    }
    __syncthreads();

    const int w = t >> 5, lane = t & 31;
    const float* Qr = Qs + lane * 65;
    float acc[8] = {};

    if (w < 4) {
        const int baserow = 31 - w * 8;
#pragma unroll
        for (int d = 0; d < 64; d++) {
            const float qv = Qr[d];
#pragma unroll
            for (int j = 0; j < 8; j++)
                acc[j] = fmaf(qv, Hs[(baserow - j) * 65 + d], acc[j]);
        }
        float* out = g_RH + ((size_t)bh * SEQ + qh * 32 + lane) * HH + w * 8;
        *(float4*)out       = make_float4(acc[0]*8.f, acc[1]*8.f, acc[2]*8.f, acc[3]*8.f);
        *(float4*)(out + 4) = make_float4(acc[4]*8.f, acc[5]*8.f, acc[6]*8.f, acc[7]*8.f);
    } else {
        const int baserow = lane + 31 - (w - 4) * 8;
#pragma unroll
        for (int d = 0; d < 64; d++) {
            const float qv = Qr[d];
#pragma unroll
            for (int j = 0; j < 8; j++)
                acc[j] = fmaf(qv, Wt[(baserow - j) * 65 + d], acc[j]);
        }
        float* out = g_RW + ((size_t)bh * SEQ + qh * 32 + lane) * WWID
                     + (w - 4) * 8;
        *(float4*)out       = make_float4(acc[0]*8.f, acc[1]*8.f, acc[2]*8.f, acc[3]*8.f);
        *(float4*)(out + 4) = make_float4(acc[4]*8.f, acc[5]*8.f, acc[6]*8.f, acc[7]*8.f);
    }
}

// ===========================================================================
// fp16 flash attention.  Block = 128 queries, 4 warps x 32 queries (2 A-sub-
// tiles per warp -> every K/V B-fragment feeds 2 mma).  64-key tiles handled
// in 32-key halves to bound transient registers.  Smem = combined 4608-word
// buffer (Ks rows 0-63 keys, Vs rows 0-63 d).  rw idx = key&31 = nt*8+2*t4.
// ===========================================================================
__global__ void __launch_bounds__(128, 2) flash_f16_kernel()
{
    __shared__ unsigned sm[4608];        // Ks = sm[0..2303], Vs = sm[2304..]
    unsigned* Ks = sm;
    unsigned* Vs = sm + 2304;

    const int t = threadIdx.x, w = t >> 5, lane = t & 31;
    const int g = lane >> 2, t4 = lane & 3;
    const int bh = blockIdx.y;
    const int q0 = blockIdx.x * 128;
    const int qrow = w * 32;

    const __half* Kg  = g_K  + (size_t)bh * SEQ * HD;
    const __half* Vtg = g_Vt + (size_t)bh * HD * SEQ;

    // ---- stage Q tile (128 rows) across the whole buffer, pull fragments ---
    {
        const __half* Qg = g_Q + ((size_t)bh * SEQ + q0) * HD;
#pragma unroll
        for (int j = 0; j < 8; j++) {
            const int idx = t + 128 * j;
            const int row = idx >> 3, u4 = idx & 7;
            *(uint4*)&sm[row * 36 + u4 * 4] =
                *(const uint4*)(Qg + (size_t)row * HD + u4 * 8);
        }
        __syncthreads();
    }
    unsigned qa[2][4][4];
#pragma unroll
    for (int s = 0; s < 2; s++) {
        const int r0 = qrow + s * 16;
#pragma unroll
        for (int c = 0; c < 4; c++) {
            const int kw = c * 8;
            qa[s][c][0] = sm[(r0 + g) * 36 + kw + t4];
            qa[s][c][1] = sm[(r0 + g + 8) * 36 + kw + t4];
            qa[s][c][2] = sm[(r0 + g) * 36 + kw + t4 + 4];
            qa[s][c][3] = sm[(r0 + g + 8) * 36 + kw + t4 + 4];
        }
    }
    __syncthreads();   // all Q frags read before tile 0 overwrites the buffer

    // ---- rw bias (tile-invariant, 32-wide) into regs; row groups r=0..3 ----
    const float* RWg = g_RW + ((size_t)bh * SEQ + q0) * 32;
    float rwr[4][4][2];
#pragma unroll
    for (int r = 0; r < 4; r++) {
        const int qr = (qrow + r * 8 + g) * 32;
#pragma unroll
        for (int nb = 0; nb < 4; nb++) {
            rwr[r][nb][0] = __ldg(RWg + qr + nb * 8 + 2 * t4);
            rwr[r][nb][1] = __ldg(RWg + qr + nb * 8 + 2 * t4 + 1);
        }
    }
    const float* RHg = g_RH + ((size_t)bh * SEQ + q0) * 32;

    float o[2][8][4] = {};
    float l[4] = {0.f, 0.f, 0.f, 0.f};

    for (int kt = 0; kt < 16; kt++) {
        uint4 kreg[4], vreg[4];
#pragma unroll
        for (int j = 0; j < 4; j++) {
            const int idx = t + 128 * j;
            const int row = idx >> 3, u4 = idx & 7;
            kreg[j] = *(const uint4*)(Kg + (size_t)(kt * 64 + row) * HD
                                      + u4 * 8);
            vreg[j] = *(const uint4*)(Vtg + (size_t)row * SEQ + kt * 64
                                      + u4 * 8);
        }
        __syncthreads();
#pragma unroll
        for (int j = 0; j < 4; j++) {
            const int idx = t + 128 * j;
            const int row = idx >> 3, u4 = idx & 7;
            *(uint4*)&Ks[row * 36 + u4 * 4] = kreg[j];
            *(uint4*)&Vs[row * 36 + u4 * 4] = vreg[j];
        }
        __syncthreads();

        // ---- process the 64-key tile in two 32-key halves --------------------
#pragma unroll
        for (int h2 = 0; h2 < 2; h2++) {
            // S = Q @ K^T for this half
            float sreg[2][4][4] = {};
#pragma unroll
            for (int c = 0; c < 4; c++) {
                const int kw = c * 8;
#pragma unroll
                for (int nt = 0; nt < 4; nt++) {
                    const int kr = (h2 * 32 + nt * 8 + g) * 36 + kw;
                    const unsigned b0 = Ks[kr + t4];
                    const unsigned b1 = Ks[kr + t4 + 4];
                    mma_f16(sreg[0][nt], qa[0][c], b0, b1);
                    mma_f16(sreg[1][nt], qa[1][c], b0, b1);
                }
            }

            // softmax -> packed P fragments
            float rh[4];
#pragma unroll
            for (int r = 0; r < 4; r++)
                rh[r] = __ldg(RHg + (qrow + r * 8 + g) * 32 + kt * 2 + h2);
            unsigned pk[2][4][2];
#pragma unroll
            for (int s = 0; s < 2; s++) {
#pragma unroll
                for (int nt = 0; nt < 4; nt++) {
                    const float bA = rh[s * 2];
                    const float bB = rh[s * 2 + 1];
                    const float p00 = __expf(fminf(
                        sreg[s][nt][0] + bA + rwr[s * 2][nt][0], 60.f));
                    const float p01 = __expf(fminf(
                        sreg[s][nt][1] + bA + rwr[s * 2][nt][1], 60.f));
                    const float p10 = __expf(fminf(
                        sreg[s][nt][2] + bB + rwr[s * 2 + 1][nt][0], 60.f));
                    const float p11 = __expf(fminf(
                        sreg[s][nt][3] + bB + rwr[s * 2 + 1][nt][1], 60.f));
                    l[s * 2]     += p00 + p01;
                    l[s * 2 + 1] += p10 + p11;
                    pk[s][nt][0] = pack_half2(p00, p01);
                    pk[s][nt][1] = pack_half2(p10, p11);
                }
            }

            // O += P @ V for this half
#pragma unroll
            for (int kv = 0; kv < 2; kv++) {
                unsigned ap[2][4];
#pragma unroll
                for (int s = 0; s < 2; s++) {
                    ap[s][0] = pk[s][2 * kv][0];
                    ap[s][1] = pk[s][2 * kv][1];
                    ap[s][2] = pk[s][2 * kv + 1][0];
                    ap[s][3] = pk[s][2 * kv + 1][1];
                }
                const int kwv = h2 * 16 + kv * 8;
#pragma unroll
                for (int db = 0; db < 8; db++) {
                    const int vr = (db * 8 + g) * 36 + kwv;
                    const unsigned b0 = Vs[vr + t4];
                    const unsigned b1 = Vs[vr + t4 + 4];
                    mma_f16(o[0][db], ap[0], b0, b1);
                    mma_f16(o[1][db], ap[1], b0, b1);
                }
            }
        }
    }

    // ---- finalize -----------------------------------------------------------
    float inv[4];
#pragma unroll
    for (int r = 0; r < 4; r++) {
        float lv = l[r];
        lv += __shfl_xor_sync(0xffffffffu, lv, 1);
        lv += __shfl_xor_sync(0xffffffffu, lv, 2);
        inv[r] = 1.f / lv;
    }

    const int b_ = bh / NHEADS, h = bh - b_ * NHEADS;
#pragma unroll
    for (int s = 0; s < 2; s++) {
        const int rowA = q0 + qrow + s * 16 + g;
        const int rowB = rowA + 8;
        __half* OgA = g_ATT + ((size_t)b_ * SEQ + rowA) * CDIM + h * HD;
        __half* OgB = g_ATT + ((size_t)b_ * SEQ + rowB) * CDIM + h * HD;
        const float invA = inv[s * 2], invB = inv[s * 2 + 1];
#pragma unroll
        for (int db = 0; db < 8; db++) {
            const int c = db * 8 + 2 * t4;
            OgA[c]     = __float2half(o[s][db][0] * invA);
            OgA[c + 1] = __float2half(o[s][db][1] * invA);
            OgB[c]     = __float2half(o[s][db][2] * invB);
            OgB[c + 1] = __float2half(o[s][db][3] * invB);
        }
    }
}

// ===========================================================================
// launch
// ===========================================================================
extern "C" void kernel_launch(void* const* d_in, const int* in_sizes, int n_in,
                              void* d_out, int out_size)
{
    const float* hidden = (const float*)d_in[0];
    const float* qkv_w  = (const float*)d_in[1];
    const float* qkv_b  = (const float*)d_in[2];
    const float* proj_w = (const float*)d_in[3];
    const float* proj_b = (const float*)d_in[4];
    const float* rph    = (const float*)d_in[5];
    const float* rpw    = (const float*)d_in[6];
    float* out = (float*)d_out;

    __half *x_ptr = nullptr, *w1t_ptr = nullptr, *w2t_ptr = nullptr,
           *att_ptr = nullptr;
    cudaGetSymbolAddress((void**)&x_ptr,   g_X);
    cudaGetSymbolAddress((void**)&w1t_ptr, g_W1t);
    cudaGetSymbolAddress((void**)&w2t_ptr, g_W2t);
    cudaGetSymbolAddress((void**)&att_ptr, g_ATT);

    // pre-convert hidden; transpose+convert weights
    {
        const int nX = BATCH * SEQ * CDIM / 4;
        cvt_kernel<<<(nX + 255) / 256, 256>>>((const float4*)hidden,
                                              (uint2*)x_ptr, nX);
        transpose_cvt_kernel<<<dim3(N_QKV / 32, CDIM / 32), 256>>>(
            qkv_w, w1t_ptr, CDIM, N_QKV);
        transpose_cvt_kernel<<<dim3(CDIM / 32, CDIM / 32), 256>>>(
            proj_w, w2t_ptr, CDIM, CDIM);
    }

    gemm_f16_kernel<true>
        <<<dim3(N_QKV / 128, (BATCH * SEQ) / 128), 128>>>(
            x_ptr, w1t_ptr, qkv_b, nullptr);
    rel_kernel<<<dim3(HH, BHEADS), 256>>>(rph, rpw);
    flash_f16_kernel<<<dim3(SEQ / 128, BHEADS), 128>>>();
    gemm_f16_kernel<false>
        <<<dim3(CDIM / 128, (BATCH * SEQ) / 128), 128>>>(
            att_ptr, w2t_ptr, proj_b, out);
}